// round 17
// baseline (speedup 1.0000x reference)
#include <cuda_runtime.h>
#include <cstdint>

// Problem constants (fixed by the reference)
#define NB 4
#define NN 10000
#define NE 160000
#define HH 128
#define FF 32
#define MM 256
#define BN (NB * NN)
#define EBLK 64
#define BLOCKS_PER_BATCH (NE / EBLK)  // 2500
#define NBLK (NB * BLOCKS_PER_BATCH)  // 10000 edge blocks
#define PERSIST_CTAS 592              // 148 SMs x 2 CTAs x 2 waves of coverage

// Expected element counts (for input identification)
#define SZ_HIDDEN (NB * NN * HH)        // 5,120,000
#define SZ_EF     (NB * NE * FF)        // 20,480,000
#define SZ_IDX    (NB * NE)             // 640,000
#define SZ_W      ((FF + 2 * HH) * MM)  // 73,728
#define SZ_B      (MM)                  // 256

// Scratch
__device__ float g_Ps[(size_t)BN * MM];
__device__ float g_Pt[(size_t)BN * MM];
__device__ int g_src[SZ_IDX];
__device__ int g_tgt[SZ_IDX];
__device__ int g_is64[2];

// ---- packed f32x2 helpers (Blackwell sm_100+: 2x fp32 FMA rate) ----
__device__ __forceinline__ unsigned long long pack2(float x) {
    unsigned long long r;
    asm("mov.b64 %0, {%1, %1};" : "=l"(r) : "f"(x));
    return r;
}
__device__ __forceinline__ void unpack2(unsigned long long p, float& lo, float& hi) {
    asm("mov.b64 {%0, %1}, %2;" : "=f"(lo), "=f"(hi) : "l"(p));
}
#define FFMA2(d, a, b, c) \
    asm("fma.rn.f32x2 %0, %1, %2, %3;" : "=l"(d) : "l"(a), "l"(b), "l"(c))

// ---------------------------------------------------------------------------
// Index dtype detection (reads only first 512 B — in-bounds for i32 or i64).
// ---------------------------------------------------------------------------
__global__ void detect_idx_kernel(const int* __restrict__ raw_a,
                                  const int* __restrict__ raw_b) {
    if (threadIdx.x == 0 && blockIdx.x == 0) {
        int oa = 0, ob = 0;
#pragma unroll
        for (int j = 1; j < 128; j += 2) { oa |= raw_a[j]; ob |= raw_b[j]; }
        g_is64[0] = (oa == 0) ? 1 : 0;
        g_is64[1] = (ob == 0) ? 1 : 0;
    }
}

// ---------------------------------------------------------------------------
// prep: zero the poisoned output AND normalize both index arrays (1 launch).
// ---------------------------------------------------------------------------
__global__ void prep_kernel(const void* __restrict__ raw_src,
                            const void* __restrict__ raw_tgt,
                            float4* __restrict__ out, int n4) {
    int i = blockIdx.x * blockDim.x + threadIdx.x;
    if (i < n4) out[i] = make_float4(0.f, 0.f, 0.f, 0.f);
    if (i < 2 * SZ_IDX) {
        int which = (i >= SZ_IDX) ? 1 : 0;
        int j = i - which * SZ_IDX;
        const void* raw = which ? raw_tgt : raw_src;
        int v;
        if (g_is64[which]) v = (int)((const long long*)raw)[j];
        else               v = ((const int*)raw)[j];
        v = (v < 0) ? 0 : (v >= NN ? NN - 1 : v);
        if (which == 0) g_src[j] = v; else g_tgt[j] = v;
    }
}

// ---------------------------------------------------------------------------
// Fused node projection GEMM (R15 winner, unchanged): Ps = X@Ws, Pt = X@Wt + b.
// Tile 64x64, 128 threads, 8x4 microtile x2 mats, packed f32x2 FMA.
// ---------------------------------------------------------------------------
__global__ __launch_bounds__(128) void node_proj_kernel(
    const float* __restrict__ X,
    const float* __restrict__ Ws,
    const float* __restrict__ Wt,
    const float* __restrict__ bias)
{
    __shared__ float As[16][64];
    __shared__ float Bs[16][64];
    __shared__ float Cs[16][64];

    const int rblk = blockIdx.x * 64;
    const int cblk = blockIdx.y * 64;
    const int t  = threadIdx.x;
    const int tx = t & 15;
    const int ty = t >> 4;

    unsigned long long accB2[8][2], accC2[8][2];
#pragma unroll
    for (int r = 0; r < 8; r++) {
        accB2[r][0] = 0ull; accB2[r][1] = 0ull;
        accC2[r][0] = 0ull; accC2[r][1] = 0ull;
    }

#pragma unroll 1
    for (int k0 = 0; k0 < HH; k0 += 16) {
        float4 av0, av1, bv0, bv1, cv0, cv1;
        {
            int i0 = t, i1 = t + 128;
            int r0 = i0 >> 2, kq0 = (i0 & 3) * 4;
            int r1 = i1 >> 2, kq1 = (i1 & 3) * 4;
            av0 = *(const float4*)&X[(size_t)(rblk + r0) * HH + k0 + kq0];
            av1 = *(const float4*)&X[(size_t)(rblk + r1) * HH + k0 + kq1];
            int kr0 = i0 >> 4, cq0 = (i0 & 15) * 4;
            int kr1 = i1 >> 4, cq1 = (i1 & 15) * 4;
            bv0 = *(const float4*)&Ws[(size_t)(k0 + kr0) * MM + cblk + cq0];
            bv1 = *(const float4*)&Ws[(size_t)(k0 + kr1) * MM + cblk + cq1];
            cv0 = *(const float4*)&Wt[(size_t)(k0 + kr0) * MM + cblk + cq0];
            cv1 = *(const float4*)&Wt[(size_t)(k0 + kr1) * MM + cblk + cq1];
            __syncthreads();
            As[kq0 + 0][r0] = av0.x; As[kq0 + 1][r0] = av0.y;
            As[kq0 + 2][r0] = av0.z; As[kq0 + 3][r0] = av0.w;
            As[kq1 + 0][r1] = av1.x; As[kq1 + 1][r1] = av1.y;
            As[kq1 + 2][r1] = av1.z; As[kq1 + 3][r1] = av1.w;
            *(float4*)&Bs[kr0][cq0] = bv0;
            *(float4*)&Bs[kr1][cq1] = bv1;
            *(float4*)&Cs[kr0][cq0] = cv0;
            *(float4*)&Cs[kr1][cq1] = cv1;
            __syncthreads();
        }

#pragma unroll
        for (int k = 0; k < 16; k++) {
            float4 a0 = *(const float4*)&As[k][ty * 8];
            float4 a1 = *(const float4*)&As[k][ty * 8 + 4];
            ulonglong2 b2 = *(const ulonglong2*)&Bs[k][tx * 4];
            ulonglong2 c2 = *(const ulonglong2*)&Cs[k][tx * 4];
            float ar[8] = {a0.x, a0.y, a0.z, a0.w, a1.x, a1.y, a1.z, a1.w};
#pragma unroll
            for (int r = 0; r < 8; r++) {
                unsigned long long ap = pack2(ar[r]);
                FFMA2(accB2[r][0], ap, b2.x, accB2[r][0]);
                FFMA2(accB2[r][1], ap, b2.y, accB2[r][1]);
                FFMA2(accC2[r][0], ap, c2.x, accC2[r][0]);
                FFMA2(accC2[r][1], ap, c2.y, accC2[r][1]);
            }
        }
    }

    float4 bvv = *(const float4*)&bias[cblk + tx * 4];

#pragma unroll
    for (int r = 0; r < 8; r++) {
        int row = rblk + ty * 8 + r;
        float4 o1, o2;
        unpack2(accB2[r][0], o1.x, o1.y);
        unpack2(accB2[r][1], o1.z, o1.w);
        unpack2(accC2[r][0], o2.x, o2.y);
        unpack2(accC2[r][1], o2.z, o2.w);
        o2.x += bvv.x; o2.y += bvv.y; o2.z += bvv.z; o2.w += bvv.w;
        *(float4*)&g_Ps[(size_t)row * MM + cblk + tx * 4] = o1;
        *(float4*)&g_Pt[(size_t)row * MM + cblk + tx * 4] = o2;
    }
}

// ---------------------------------------------------------------------------
// PERSISTENT edge kernel (R15 winning shape: 256 thr, 8 warps, 8e x 8c/thread).
// grid = PERSIST_CTAS; each CTA stages Wf ONCE, then grid-strides over the
// 10000 edge blocks re-staging only efs (8 KB) + indices per iteration.
// f32x2 GEMM; phase-split epilogue (batched gathers -> relu -> batched red.v4).
// ---------------------------------------------------------------------------
__global__ __launch_bounds__(256, 2) void edge_kernel(
    const float* __restrict__ ef,   // [NB*NE, 32]
    const float* __restrict__ W,    // first 32 rows of W_msg, row stride 256
    float* __restrict__ out)        // [BN, 256]
{
    __shared__ float Wf[FF][MM];            // 32 KB (staged once)
    __shared__ float efs_t[FF][EBLK + 8];   // [k][edge]
    __shared__ int   src_s[EBLK];
    __shared__ int   tgt_s[EBLK];

    const int t = threadIdx.x;

    // Stage Wf ONCE per CTA (2048 float4)
    {
        float4* wsh = (float4*)&Wf[0][0];
        const float4* wg = (const float4*)W;
#pragma unroll
        for (int i = 0; i < 8; i++) wsh[t + 256 * i] = wg[t + 256 * i];
    }

    const int warp = t >> 5;
    const int lane = t & 31;
    const int c0 = lane * 4;
    const int c1 = c0 + 128;

#pragma unroll 1
    for (int blk = blockIdx.x; blk < NBLK; blk += PERSIST_CTAS) {
        const int b   = blk / BLOCKS_PER_BATCH;
        const int e0  = (blk % BLOCKS_PER_BATCH) * EBLK;
        const int ebase = b * NE + e0;
        const int nodebase = b * NN;

        __syncthreads();   // protect efs_t/indices from previous iteration's readers
        // Stage edge features transposed (512 float4, 2 per thread)
        {
#pragma unroll
            for (int it = 0; it < 2; it++) {
                int i = t + 256 * it;
                int r = i >> 3;
                int c = (i & 7) * 4;
                float4 v = *(const float4*)&ef[(size_t)(ebase + r) * FF + c];
                efs_t[c + 0][r] = v.x; efs_t[c + 1][r] = v.y;
                efs_t[c + 2][r] = v.z; efs_t[c + 3][r] = v.w;
            }
        }
        if (t < EBLK) {
            src_s[t] = g_src[ebase + t];
            tgt_s[t] = g_tgt[ebase + t];
        }
        __syncthreads();

        unsigned long long mA2[8][2], mB2[8][2];
#pragma unroll
        for (int j = 0; j < 8; j++) {
            mA2[j][0] = 0ull; mA2[j][1] = 0ull;
            mB2[j][0] = 0ull; mB2[j][1] = 0ull;
        }

#pragma unroll 8
        for (int k = 0; k < FF; k++) {
            float4 aA = *(const float4*)&efs_t[k][warp * 8];
            float4 aB = *(const float4*)&efs_t[k][warp * 8 + 4];
            ulonglong2 w02 = *(const ulonglong2*)&Wf[k][c0];
            ulonglong2 w12 = *(const ulonglong2*)&Wf[k][c1];
            float a[8] = {aA.x, aA.y, aA.z, aA.w, aB.x, aB.y, aB.z, aB.w};
#pragma unroll
            for (int j = 0; j < 8; j++) {
                unsigned long long ap = pack2(a[j]);
                FFMA2(mA2[j][0], ap, w02.x, mA2[j][0]);
                FFMA2(mA2[j][1], ap, w02.y, mA2[j][1]);
                FFMA2(mB2[j][0], ap, w12.x, mB2[j][0]);
                FFMA2(mB2[j][1], ap, w12.y, mB2[j][1]);
            }
        }

        // Unpack accumulators
        float4 mA[8], mB[8];
#pragma unroll
        for (int j = 0; j < 8; j++) {
            unpack2(mA2[j][0], mA[j].x, mA[j].y);
            unpack2(mA2[j][1], mA[j].z, mA[j].w);
            unpack2(mB2[j][0], mB[j].x, mB[j].y);
            unpack2(mB2[j][1], mB[j].z, mB[j].w);
        }

        // ---- Epilogue phase A: batched gathers + relu ----
        int sg[8], dg[8];
#pragma unroll
        for (int j = 0; j < 8; j++) {
            const int e = warp * 8 + j;
            sg[j] = nodebase + src_s[e];
            dg[j] = nodebase + tgt_s[e];
        }

#pragma unroll
        for (int j = 0; j < 8; j++) {
            float4 ps0 = *(const float4*)&g_Ps[(size_t)sg[j] * MM + c0];
            float4 pt0 = *(const float4*)&g_Pt[(size_t)dg[j] * MM + c0];
            mA[j].x = fmaxf(mA[j].x + ps0.x + pt0.x, 0.f);
            mA[j].y = fmaxf(mA[j].y + ps0.y + pt0.y, 0.f);
            mA[j].z = fmaxf(mA[j].z + ps0.z + pt0.z, 0.f);
            mA[j].w = fmaxf(mA[j].w + ps0.w + pt0.w, 0.f);
        }
#pragma unroll
        for (int j = 0; j < 8; j++) {
            float4 ps1 = *(const float4*)&g_Ps[(size_t)sg[j] * MM + c1];
            float4 pt1 = *(const float4*)&g_Pt[(size_t)dg[j] * MM + c1];
            mB[j].x = fmaxf(mB[j].x + ps1.x + pt1.x, 0.f);
            mB[j].y = fmaxf(mB[j].y + ps1.y + pt1.y, 0.f);
            mB[j].z = fmaxf(mB[j].z + ps1.z + pt1.z, 0.f);
            mB[j].w = fmaxf(mB[j].w + ps1.w + pt1.w, 0.f);
        }

        // ---- Epilogue phase B: back-to-back vector reductions ----
#pragma unroll
        for (int j = 0; j < 8; j++) {
            float* op0 = &out[(size_t)dg[j] * MM + c0];
            asm volatile("red.global.add.v4.f32 [%0], {%1, %2, %3, %4};"
                         :: "l"(op0), "f"(mA[j].x), "f"(mA[j].y), "f"(mA[j].z), "f"(mA[j].w)
                         : "memory");
        }
#pragma unroll
        for (int j = 0; j < 8; j++) {
            float* op1 = &out[(size_t)dg[j] * MM + c1];
            asm volatile("red.global.add.v4.f32 [%0], {%1, %2, %3, %4};"
                         :: "l"(op1), "f"(mB[j].x), "f"(mB[j].y), "f"(mB[j].z), "f"(mB[j].w)
                         : "memory");
        }
    }
}

// ---------------------------------------------------------------------------
// kernel_launch — inputs identified BY ELEMENT COUNT; index dtype detected
// on device. Output f32 [4,10000,256].
// ---------------------------------------------------------------------------
extern "C" void kernel_launch(void* const* d_in, const int* in_sizes, int n_in,
                              void* d_out, int out_size) {
    const float* hidden = nullptr;
    const float* ef     = nullptr;
    const void*  srcs   = nullptr;
    const void*  tgts   = nullptr;
    const float* W      = nullptr;
    const float* bmsg   = nullptr;

    for (int i = 0; i < n_in; i++) {
        switch (in_sizes[i]) {
            case SZ_HIDDEN: hidden = (const float*)d_in[i]; break;
            case SZ_EF:     ef     = (const float*)d_in[i]; break;
            case SZ_W:      W      = (const float*)d_in[i]; break;
            case SZ_B:      bmsg   = (const float*)d_in[i]; break;
            case SZ_IDX:
                if (!srcs) srcs = d_in[i];
                else       tgts = d_in[i];
                break;
            default: break;
        }
    }
    float* out = (float*)d_out;

    // 0) detect index dtype; then prep = zero output + normalize indices
    detect_idx_kernel<<<1, 32>>>((const int*)srcs, (const int*)tgts);
    int n4 = out_size / 4;
    prep_kernel<<<(n4 + 255) / 256, 256>>>(srcs, tgts, (float4*)out, n4);

    // 1) fused node projections: Ps = h @ W[32:160], Pt = h @ W[160:288] + b
    dim3 gA(BN / 64, MM / 64);
    node_proj_kernel<<<gA, 128>>>(hidden,
                                  W + (size_t)FF * MM,
                                  W + (size_t)(FF + HH) * MM,
                                  bmsg);

    // 2) persistent per-edge message + scatter-add (Wf staged once per CTA)
    edge_kernel<<<PERSIST_CTAS, 256>>>(ef, W, out);
}